// round 4
// baseline (speedup 1.0000x reference)
#include <cuda_runtime.h>
#include <cuda_bf16.h>
#include <math.h>
#include <stdint.h>

// ---------------------------------------------------------------------------
// Problem constants
// ---------------------------------------------------------------------------
#define B_N 8192
#define D_N 512
#define K_N 20

// GEMM tiling
#define BM 128
#define BNC 128               // cols per CTA
#define CK 64                 // K elems per chunk (64 bf16 = 128B row)
#define NC (D_N / CK)         // 8 chunks
#define NBLK (B_N / BM)       // 64 row/col blocks
#define NSEG NBLK             // 64 partial-topk segments per row
#define NTILE (NBLK * (NBLK + 1) / 2)  // 2080 triangular tiles
#define LDC 129

#define STG_A 16384           // 128*64*2 bytes
#define STG_BUF 32768         // A+B per stage
#define NSTG 3
#define SMEM_BYTES (NSTG * STG_BUF)   // 98304 >= Csh 128*129*4 = 66048

// ---------------------------------------------------------------------------
// Scratch (__device__ globals — allocation-free)
// ---------------------------------------------------------------------------
__device__ __align__(128) __nv_bfloat16 g_xb[B_N * D_N];   // normalized rows (bf16)
__device__ float g_pvals[(size_t)B_N * NSEG * K_N];
__device__ int   g_pidx [(size_t)B_N * NSEG * K_N];
__device__ float g_blocksum[B_N / 128];

// ---------------------------------------------------------------------------
// PTX helpers (baseline ISA only: cp.async, ldmatrix, mma.sync)
// ---------------------------------------------------------------------------
__device__ __forceinline__ uint32_t smem_u32(const void* p) {
    uint32_t a;
    asm("{ .reg .u64 t; cvta.to.shared.u64 t, %1; cvt.u32.u64 %0, t; }" : "=r"(a) : "l"(p));
    return a;
}

__device__ __forceinline__ void cp_async16(uint32_t dst, const void* src) {
    asm volatile("cp.async.cg.shared.global [%0], [%1], 16;" :: "r"(dst), "l"(src) : "memory");
}
#define CP_COMMIT() asm volatile("cp.async.commit_group;" ::: "memory")
#define CP_WAIT2()  asm volatile("cp.async.wait_group 2;" ::: "memory")
#define CP_WAIT1()  asm volatile("cp.async.wait_group 1;" ::: "memory")
#define CP_WAIT0()  asm volatile("cp.async.wait_group 0;" ::: "memory")

#define LDSM_X4(r0, r1, r2, r3, addr)                                        \
    asm volatile("ldmatrix.sync.aligned.m8n8.x4.shared.b16 {%0,%1,%2,%3}, [%4];" \
                 : "=r"(r0), "=r"(r1), "=r"(r2), "=r"(r3) : "r"(addr))

__device__ __forceinline__ void mma16816(float* c, uint32_t a0, uint32_t a1,
                                         uint32_t a2, uint32_t a3,
                                         uint32_t b0, uint32_t b1) {
    asm volatile(
        "mma.sync.aligned.m16n8k16.row.col.f32.bf16.bf16.f32 "
        "{%0,%1,%2,%3}, {%4,%5,%6,%7}, {%8,%9}, {%0,%1,%2,%3};"
        : "+f"(c[0]), "+f"(c[1]), "+f"(c[2]), "+f"(c[3])
        : "r"(a0), "r"(a1), "r"(a2), "r"(a3), "r"(b0), "r"(b1));
}

// ---------------------------------------------------------------------------
// 1) Row L2 normalization -> bf16
// ---------------------------------------------------------------------------
__global__ void normalize_kernel(const float* __restrict__ x) {
    __shared__ float warp_ss[4];
    __shared__ float s_inv;
    int row = blockIdx.x;
    int t = threadIdx.x;  // 128
    const float* xr = x + row * D_N;
    float v[4];
    float ss = 0.f;
#pragma unroll
    for (int i = 0; i < 4; i++) { v[i] = xr[t + 128 * i]; ss += v[i] * v[i]; }
#pragma unroll
    for (int off = 16; off > 0; off >>= 1) ss += __shfl_xor_sync(0xffffffffu, ss, off);
    if ((t & 31) == 0) warp_ss[t >> 5] = ss;
    __syncthreads();
    if (t == 0) {
        float tot = warp_ss[0] + warp_ss[1] + warp_ss[2] + warp_ss[3];
        s_inv = 1.0f / fmaxf(sqrtf(tot), 1e-12f);
    }
    __syncthreads();
    float inv = s_inv;
#pragma unroll
    for (int i = 0; i < 4; i++)
        g_xb[row * D_N + t + 128 * i] = __float2bfloat16_rn(v[i] * inv);
}

// ---------------------------------------------------------------------------
// 2) Symmetric bf16 mma.sync GEMM over triangular tiles + dual top-20 epilogue
//    256 threads = 8 warps, warp tile 64x32 (4x4 m16n8k16), 3-stage cp.async
// ---------------------------------------------------------------------------
extern __shared__ char smem_raw[];

__global__ __launch_bounds__(256, 1) void gemm_topk_mma() {
    const int tid = threadIdx.x;
    const int lane = tid & 31;
    const int wid = tid >> 5;
    const int wm = wid & 1;        // M offset 0/64
    const int wn = wid >> 1;       // N offset 0/32/64/96

    // triangular tile decode: bid -> (bi, bj), bi <= bj
    int bi = 0, rem = blockIdx.x;
    while (rem >= NBLK - bi) { rem -= NBLK - bi; bi++; }
    const int bj = bi + rem;
    const int rowBase = bi * BM;
    const int colBase = bj * BNC;

    const uint32_t sbase = smem_u32(smem_raw);
    float* Csh = (float*)smem_raw;

    // cp.async staging map: cid = tid + 256*i -> row=cid>>3, 16B-chunk=cid&7
    uint32_t soff[4], grow[4];
#pragma unroll
    for (int i = 0; i < 4; i++) {
        int cid = tid + 256 * i;
        int r = cid >> 3, c16 = cid & 7;
        soff[i] = (uint32_t)(r * 128 + ((c16 * 16) ^ ((r & 7) << 4)));
        grow[i] = (uint32_t)(r * (D_N * 2) + c16 * 16);
    }
    const char* Agbase = (const char*)g_xb + (size_t)rowBase * D_N * 2;
    const char* Bgbase = (const char*)g_xb + (size_t)colBase * D_N * 2;

    // ldmatrix per-lane addressing
    const uint32_t rx = (uint32_t)((lane & 7) << 4);
    const uint32_t ah = (uint32_t)((lane >> 4) << 4);
    const uint32_t bh = (uint32_t)(((lane >> 3) & 1) << 4);
    uint32_t arow[4], brow[2];
#pragma unroll
    for (int mt = 0; mt < 4; mt++)
        arow[mt] = (uint32_t)((wm * 64 + mt * 16 + (lane & 7) + ((lane >> 3) & 1) * 8) * 128);
#pragma unroll
    for (int np = 0; np < 2; np++)
        brow[np] = (uint32_t)((wn * 32 + np * 16 + (lane & 7) + (lane >> 4) * 8) * 128);

    float acc[4][4][4];
#pragma unroll
    for (int mt = 0; mt < 4; mt++)
#pragma unroll
        for (int nt = 0; nt < 4; nt++)
#pragma unroll
            for (int q = 0; q < 4; q++) acc[mt][nt][q] = 0.f;

    // prologue: stage chunks 0..2
#pragma unroll
    for (int pc = 0; pc < NSTG; pc++) {
        uint32_t ab = sbase + pc * STG_BUF;
        uint32_t bb = ab + STG_A;
        const char* Ag = Agbase + pc * (CK * 2);
        const char* Bg = Bgbase + pc * (CK * 2);
#pragma unroll
        for (int i = 0; i < 4; i++) {
            cp_async16(ab + soff[i], Ag + grow[i]);
            cp_async16(bb + soff[i], Bg + grow[i]);
        }
        CP_COMMIT();
    }

#pragma unroll
    for (int kc = 0; kc < NC; kc++) {
        if (kc <= NC - 3) CP_WAIT2();
        else if (kc == NC - 2) CP_WAIT1();
        else CP_WAIT0();
        __syncthreads();

        const uint32_t ab = sbase + (kc % NSTG) * STG_BUF;
        const uint32_t bb = ab + STG_A;
#pragma unroll
        for (int ks = 0; ks < 4; ks++) {
            const uint32_t kbyte = (uint32_t)(ks * 32);
            uint32_t a[4][4], b[2][4];
#pragma unroll
            for (int mt = 0; mt < 4; mt++)
                LDSM_X4(a[mt][0], a[mt][1], a[mt][2], a[mt][3],
                        ab + arow[mt] + ((kbyte + ah) ^ rx));
#pragma unroll
            for (int np = 0; np < 2; np++)
                LDSM_X4(b[np][0], b[np][1], b[np][2], b[np][3],
                        bb + brow[np] + ((kbyte + bh) ^ rx));
#pragma unroll
            for (int mt = 0; mt < 4; mt++)
#pragma unroll
                for (int nt = 0; nt < 4; nt++)
                    mma16816(acc[mt][nt],
                             a[mt][0], a[mt][1], a[mt][2], a[mt][3],
                             b[nt >> 1][2 * (nt & 1)], b[nt >> 1][2 * (nt & 1) + 1]);
        }
        __syncthreads();

        if (kc + NSTG < NC) {
            uint32_t ab2 = sbase + (kc % NSTG) * STG_BUF;
            uint32_t bb2 = ab2 + STG_A;
            const char* Ag = Agbase + (kc + NSTG) * (CK * 2);
            const char* Bg = Bgbase + (kc + NSTG) * (CK * 2);
#pragma unroll
            for (int i = 0; i < 4; i++) {
                cp_async16(ab2 + soff[i], Ag + grow[i]);
                cp_async16(bb2 + soff[i], Bg + grow[i]);
            }
            CP_COMMIT();
        }
    }

    // dump accumulators to Csh (staging smem reuse; post-compute sync done above)
    {
        const int g = lane >> 2;
        const int c2 = 2 * (lane & 3);
#pragma unroll
        for (int mt = 0; mt < 4; mt++) {
            const int r0 = wm * 64 + mt * 16 + g;
#pragma unroll
            for (int nt = 0; nt < 4; nt++) {
                const int c0 = wn * 32 + nt * 8 + c2;
                Csh[r0 * LDC + c0]           = acc[mt][nt][0];
                Csh[r0 * LDC + c0 + 1]       = acc[mt][nt][1];
                Csh[(r0 + 8) * LDC + c0]     = acc[mt][nt][2];
                Csh[(r0 + 8) * LDC + c0 + 1] = acc[mt][nt][3];
            }
        }
    }
    __syncthreads();

    // dual epilogue: threads 0-127 scan rows (slot bj); 128-255 scan cols (slot bi)
    const bool colSide = (tid >= BM);
    if (!colSide || bi != bj) {
        float topv[K_N];
        int   topi[K_N];
#pragma unroll
        for (int q = 0; q < K_N; q++) { topv[q] = -2.0f; topi[q] = 0; }
        const int r = tid & (BM - 1);
        const int gi = (colSide ? colBase : rowBase) + r;   // row owning the topk list
        const int gjBase = colSide ? rowBase : colBase;     // indices being scanned
        float th = -2.0f;
        for (int c = 0; c < BNC; c++) {
            float v = colSide ? Csh[c * LDC + r] : Csh[r * LDC + c];
            int gj = gjBase + c;
            if (v > th && gj != gi) {
                int p = K_N - 1;
                while (p > 0 && topv[p - 1] < v) {
                    topv[p] = topv[p - 1];
                    topi[p] = topi[p - 1];
                    p--;
                }
                topv[p] = v;
                topi[p] = gj;
                th = topv[K_N - 1];
            }
        }
        const int slot = colSide ? bi : bj;
        float* pv = g_pvals + ((size_t)gi * NSEG + slot) * K_N;
        int*   pi = g_pidx  + ((size_t)gi * NSEG + slot) * K_N;
#pragma unroll
        for (int q = 0; q < K_N; q++) { pv[q] = topv[q]; pi[q] = topi[q]; }
    }
}

// ---------------------------------------------------------------------------
// 3) Merge 64 partial top-20 lists per row + BCE; block partial sums
// ---------------------------------------------------------------------------
__global__ void merge_loss_kernel(const int* __restrict__ labels) {
    __shared__ float sh[128];
    int row = blockIdx.x * 128 + threadIdx.x;
    float tv[K_N];
    int   ti[K_N];
#pragma unroll
    for (int q = 0; q < K_N; q++) { tv[q] = -2.0f; ti[q] = 0; }
    const float* pv = g_pvals + (size_t)row * NSEG * K_N;
    const int*   pi = g_pidx  + (size_t)row * NSEG * K_N;
    float th = -2.0f;
    for (int s = 0; s < NSEG; s++) {
        for (int q = 0; q < K_N; q++) {
            float v = pv[s * K_N + q];
            if (v <= th) break;  // segment lists are descending
            int idx = pi[s * K_N + q];
            int p = K_N - 1;
            while (p > 0 && tv[p - 1] < v) {
                tv[p] = tv[p - 1];
                ti[p] = ti[p - 1];
                p--;
            }
            tv[p] = v;
            ti[p] = idx;
            th = tv[K_N - 1];
        }
    }
    int lab = labels[row];
    float sum = 0.f;
#pragma unroll
    for (int q = 0; q < K_N; q++) {
        float pred = 0.5f * (tv[q] + 1.0f);
        float logp   = fmaxf(logf(pred), -100.0f);
        float log1mp = fmaxf(log1pf(-pred), -100.0f);
        sum += (labels[ti[q]] == lab) ? -logp : -log1mp;
    }
    sh[threadIdx.x] = sum;
    __syncthreads();
    for (int off = 64; off > 0; off >>= 1) {
        if (threadIdx.x < off) sh[threadIdx.x] += sh[threadIdx.x + off];
        __syncthreads();
    }
    if (threadIdx.x == 0) g_blocksum[blockIdx.x] = sh[0];
}

// ---------------------------------------------------------------------------
// 4) Deterministic final reduction over 64 block sums
// ---------------------------------------------------------------------------
__global__ void reduce_kernel(float* __restrict__ out) {
    __shared__ double sh[64];
    int t = threadIdx.x;
    sh[t] = (double)g_blocksum[t];
    __syncthreads();
    for (int off = 32; off > 0; off >>= 1) {
        if (t < off) sh[t] += sh[t + off];
        __syncthreads();
    }
    if (t == 0) out[0] = (float)(sh[0] / (double)((long long)B_N * K_N));
}

// ---------------------------------------------------------------------------
extern "C" void kernel_launch(void* const* d_in, const int* in_sizes, int n_in,
                              void* d_out, int out_size) {
    const float* batch  = (const float*)d_in[0];
    const int*   labels = (const int*)d_in[1];
    float* out = (float*)d_out;
    (void)in_sizes; (void)n_in; (void)out_size;

    cudaFuncSetAttribute(gemm_topk_mma, cudaFuncAttributeMaxDynamicSharedMemorySize,
                         SMEM_BYTES);

    normalize_kernel<<<B_N, 128>>>(batch);
    gemm_topk_mma<<<NTILE, 256, SMEM_BYTES>>>();
    merge_loss_kernel<<<B_N / 128, 128>>>(labels);
    reduce_kernel<<<1, 64>>>(out);
}